// round 7
// baseline (speedup 1.0000x reference)
#include <cuda_runtime.h>
#include <cuda_fp16.h>
#include <cstdint>

#define DI __device__ __forceinline__

static constexpr int B_ = 4, H_ = 8, S_ = 2048, D_ = 1024, KQ_ = 128;

// ---------------- scratch (device globals; no allocations allowed) ----------------
__device__ __half g_MT[(size_t)H_ * D_ * D_];    //  16 MB  M^T[h][j][d]
__device__ __half g_TWo[(size_t)H_ * D_ * D_];   //  16 MB  Wo^T per head [h][j][v]
__device__ __half g_WvH[(size_t)H_ * D_ * D_];   //  16 MB  Wv fp16 [h][d][v]
__device__ __half g_TWq[(size_t)H_ * KQ_ * D_];  //   2 MB  Wq^T [h][kq][d]
__device__ __half g_TWk[(size_t)H_ * KQ_ * D_];  //   2 MB
__device__ __half g_zh[(size_t)B_ * S_ * D_];    //  16 MB
__device__ __half g_yh[(size_t)B_ * S_ * D_];    //  16 MB
__device__ __half g_Qh[(size_t)B_ * H_ * S_ * KQ_];  // 16 MB
__device__ __half g_Kh[(size_t)B_ * H_ * S_ * KQ_];  // 16 MB
__device__ __half g_UT[(size_t)B_ * H_ * D_ * S_];   // 128 MB U^T[b,h][j][t]
__device__ float g_P[(size_t)B_ * H_ * S_ * S_];     // 512 MB scores fp32 / P fp16 packed
__device__ float g_cvec[D_];
__device__ float g_cpart[32 * D_];

// ---------------- helpers ----------------
DI uint32_t smem_u32(const void* p) {
    uint32_t a;
    asm("{ .reg .u64 t; cvta.to.shared.u64 t, %1; cvt.u32.u64 %0, t; }" : "=r"(a) : "l"(p));
    return a;
}
DI void mma_f16(float c[4], uint32_t a0, uint32_t a1, uint32_t a2, uint32_t a3,
                uint32_t b0, uint32_t b1) {
    asm volatile(
        "mma.sync.aligned.m16n8k16.row.col.f32.f16.f16.f32 "
        "{%0,%1,%2,%3}, {%4,%5,%6,%7}, {%8,%9}, {%0,%1,%2,%3};"
        : "+f"(c[0]), "+f"(c[1]), "+f"(c[2]), "+f"(c[3])
        : "r"(a0), "r"(a1), "r"(a2), "r"(a3), "r"(b0), "r"(b1));
}
DI void ldsm4(uint32_t r[4], uint32_t a) {
    asm volatile("ldmatrix.sync.aligned.m8n8.x4.shared.b16 {%0,%1,%2,%3}, [%4];"
                 : "=r"(r[0]), "=r"(r[1]), "=r"(r[2]), "=r"(r[3]) : "r"(a));
}
DI void cp16(uint32_t d, const void* s) {
    asm volatile("cp.async.cg.shared.global [%0], [%1], 16;" :: "r"(d), "l"(s));
}
DI void cp_commit() { asm volatile("cp.async.commit_group;" ::: "memory"); }

DI void cwrite(__half* p, float a, float b) {
    *reinterpret_cast<__half2*>(p) = __floats2half2_rn(a, b);
}
DI void cwrite(float* p, float a, float b) {
    *reinterpret_cast<float2*>(p) = make_float2(a, b);
}

// ======================= fp16 NT GEMM, 128x128 CTA, 3-stage =======================
// (used for the small-K / tiny-N GEMMs: Q, K, scores)
template <typename CT>
__global__ __launch_bounds__(256, 2) void nt_gemm(
    const __half* __restrict__ Ag, const __half* __restrict__ Bg,
    CT* __restrict__ Cg, const float* __restrict__ bias,
    int kchunks, int lda, int ldb, int ldc,
    long long sA1, long long sA2, long long sB1, long long sB2,
    long long sC1, long long sC2, int Z2, int sbias2, float alpha,
    int hshift, long long sAh, long long sBh)
{
    __shared__ __align__(128) uint32_t sAs[3][2048];
    __shared__ __align__(128) uint32_t sBs[3][2048];

    const int tid = threadIdx.x, lane = tid & 31, wid = tid >> 5;
    const int wm = (wid & 1) * 64, wn = (wid >> 1) * 32;
    const int g = lane >> 2, q = lane & 3;

    const int z = blockIdx.z, z1 = z / Z2, z2 = z % Z2;
    const __half* A = Ag + z1 * sA1 + z2 * sA2;
    const __half* Bp = Bg + z1 * sB1 + z2 * sB2;
    CT* C = Cg + z1 * sC1 + z2 * sC2;
    const int bm = blockIdx.y * 128, bn = blockIdx.x * 128;

    uint32_t dst[2];
    long long aoff[2], boff[2];
#pragma unroll
    for (int i = 0; i < 2; i++) {
        int qid = tid + i * 256;
        int lr = qid >> 2, lc = qid & 3;
        dst[i] = (uint32_t)((lr * 4 + (lc ^ ((lr >> 1) & 3))) << 4);
        aoff[i] = (long long)(bm + lr) * lda + lc * 8;
        boff[i] = (long long)(bn + lr) * ldb + lc * 8;
    }

    const uint32_t sAb = smem_u32(&sAs[0][0]);
    const uint32_t sBb = smem_u32(&sBs[0][0]);

    const int l15 = lane & 15, hs = lane >> 4;
    uint32_t arow[4], axor[4], brow[2], bxor[2];
#pragma unroll
    for (int mt = 0; mt < 4; mt++) {
        int rr = wm + mt * 16 + l15;
        arow[mt] = (uint32_t)(rr * 64);
        axor[mt] = (uint32_t)((rr >> 1) & 3);
    }
#pragma unroll
    for (int np = 0; np < 2; np++) {
        int nn = wn + np * 16 + l15;
        brow[np] = (uint32_t)(nn * 64);
        bxor[np] = (uint32_t)((nn >> 1) & 3);
    }

    float acc[4][4][4];
#pragma unroll
    for (int i = 0; i < 4; i++)
#pragma unroll
        for (int j = 0; j < 4; j++)
#pragma unroll
            for (int k = 0; k < 4; k++) acc[i][j][k] = 0.f;

    const int hmask = (hshift < 30) ? ((1 << hshift) - 1) : 0x3FFFFFFF;

    auto issue = [&](int c, int st) {
        const __half* Ac = A + (long long)(c >> hshift) * sAh + (c & hmask) * 32;
        const __half* Bc = Bp + (long long)(c >> hshift) * sBh + (c & hmask) * 32;
        const uint32_t a0 = sAb + st * 8192, b0 = sBb + st * 8192;
#pragma unroll
        for (int i = 0; i < 2; i++) {
            cp16(a0 + dst[i], Ac + aoff[i]);
            cp16(b0 + dst[i], Bc + boff[i]);
        }
        cp_commit();
    };

    issue(0, 0);
    if (kchunks > 1) issue(1, 1);

    for (int c = 0; c < kchunks; c++) {
        if (c + 1 < kchunks)
            asm volatile("cp.async.wait_group 1;" ::: "memory");
        else
            asm volatile("cp.async.wait_group 0;" ::: "memory");
        __syncthreads();
        if (c + 2 < kchunks) issue(c + 2, (c + 2) % 3);

        const int st = c % 3;
        const uint32_t aB = sAb + st * 8192, bB = sBb + st * 8192;
#pragma unroll
        for (int s = 0; s < 2; s++) {
            uint32_t af[4][4], bf[4][2];
            const uint32_t cc = (uint32_t)(2 * s + hs);
#pragma unroll
            for (int mt = 0; mt < 4; mt++)
                ldsm4(af[mt], aB + arow[mt] + ((cc ^ axor[mt]) << 4));
#pragma unroll
            for (int np = 0; np < 2; np++) {
                uint32_t t4[4];
                ldsm4(t4, bB + brow[np] + ((cc ^ bxor[np]) << 4));
                bf[2 * np][0] = t4[0];
                bf[2 * np][1] = t4[2];
                bf[2 * np + 1][0] = t4[1];
                bf[2 * np + 1][1] = t4[3];
            }
#pragma unroll
            for (int mt = 0; mt < 4; mt++)
#pragma unroll
                for (int nt = 0; nt < 4; nt++)
                    mma_f16(acc[mt][nt], af[mt][0], af[mt][1], af[mt][2], af[mt][3],
                            bf[nt][0], bf[nt][1]);
        }
    }

    const float* bp = bias ? bias + (long long)z2 * sbias2 : nullptr;
#pragma unroll
    for (int mt = 0; mt < 4; mt++) {
#pragma unroll
        for (int nt = 0; nt < 4; nt++) {
            int r = bm + wm + mt * 16 + g;
            int cc = bn + wn + nt * 8 + q * 2;
            float b0v = bp ? bp[cc] : 0.f;
            float b1v = bp ? bp[cc + 1] : 0.f;
            cwrite(C + (long long)r * ldc + cc,
                   alpha * acc[mt][nt][0] + b0v, alpha * acc[mt][nt][1] + b1v);
            cwrite(C + (long long)(r + 8) * ldc + cc,
                   alpha * acc[mt][nt][2] + b0v, alpha * acc[mt][nt][3] + b1v);
        }
    }
}

// ======================= fp16 NT GEMM, 256x128 CTA, 4-stage =======================
// 8 warps, warp tile 64x64.  Dynamic smem: 4 stages x (16KB A + 8KB B) = 96KB.
template <typename CT>
__global__ __launch_bounds__(256, 1) void nt_gemm_big(
    const __half* __restrict__ Ag, const __half* __restrict__ Bg,
    CT* __restrict__ Cg, const float* __restrict__ bias,
    int kchunks, int lda, int ldb, int ldc,
    long long sA1, long long sA2, long long sB1, long long sB2,
    long long sC1, long long sC2, int Z2, int sbias2, float alpha,
    int hshift, long long sAh, long long sBh)
{
    extern __shared__ __align__(128) uint32_t dyn_smem[];
    const uint32_t sb = smem_u32(dyn_smem);

    const int tid = threadIdx.x, lane = tid & 31, wid = tid >> 5;
    const int wm = (wid & 3) * 64, wn = (wid >> 2) * 64;
    const int g = lane >> 2, q = lane & 3;

    const int z = blockIdx.z, z1 = z / Z2, z2 = z % Z2;
    const __half* A = Ag + z1 * sA1 + z2 * sA2;
    const __half* Bp = Bg + z1 * sB1 + z2 * sB2;
    CT* C = Cg + z1 * sC1 + z2 * sC2;
    const int bm = blockIdx.y * 256, bn = blockIdx.x * 128;

    // loader: A 4x16B, B 2x16B per thread per chunk
    uint32_t dstA[4], dstB[2];
    long long aoff[4], boff[2];
#pragma unroll
    for (int i = 0; i < 4; i++) {
        int qid = tid + i * 256;
        int lr = qid >> 2, lc = qid & 3;
        dstA[i] = (uint32_t)((lr * 4 + (lc ^ ((lr >> 1) & 3))) << 4);
        aoff[i] = (long long)(bm + lr) * lda + lc * 8;
    }
#pragma unroll
    for (int i = 0; i < 2; i++) {
        int qid = tid + i * 256;
        int lr = qid >> 2, lc = qid & 3;
        dstB[i] = (uint32_t)((lr * 4 + (lc ^ ((lr >> 1) & 3))) << 4);
        boff[i] = (long long)(bn + lr) * ldb + lc * 8;
    }

    const int l15 = lane & 15, hs = lane >> 4;
    uint32_t arow[4], axor[4], brow[4], bxor[4];
#pragma unroll
    for (int mt = 0; mt < 4; mt++) {
        int rr = wm + mt * 16 + l15;
        arow[mt] = (uint32_t)(rr * 64);
        axor[mt] = (uint32_t)((rr >> 1) & 3);
    }
#pragma unroll
    for (int np = 0; np < 4; np++) {
        int nn = wn + np * 16 + l15;
        brow[np] = (uint32_t)(nn * 64);
        bxor[np] = (uint32_t)((nn >> 1) & 3);
    }

    float acc[4][8][4];
#pragma unroll
    for (int i = 0; i < 4; i++)
#pragma unroll
        for (int j = 0; j < 8; j++)
#pragma unroll
            for (int k = 0; k < 4; k++) acc[i][j][k] = 0.f;

    const int hmask = (hshift < 30) ? ((1 << hshift) - 1) : 0x3FFFFFFF;

    auto issue = [&](int c, int st) {
        const __half* Ac = A + (long long)(c >> hshift) * sAh + (c & hmask) * 32;
        const __half* Bc = Bp + (long long)(c >> hshift) * sBh + (c & hmask) * 32;
        const uint32_t a0 = sb + st * 24576, b0 = a0 + 16384;
#pragma unroll
        for (int i = 0; i < 4; i++) cp16(a0 + dstA[i], Ac + aoff[i]);
#pragma unroll
        for (int i = 0; i < 2; i++) cp16(b0 + dstB[i], Bc + boff[i]);
        cp_commit();
    };

    issue(0, 0);
    if (kchunks > 1) issue(1, 1);
    if (kchunks > 2) issue(2, 2);

    for (int c = 0; c < kchunks; c++) {
        const int rem = kchunks - 1 - c;
        if (rem >= 2)
            asm volatile("cp.async.wait_group 2;" ::: "memory");
        else if (rem == 1)
            asm volatile("cp.async.wait_group 1;" ::: "memory");
        else
            asm volatile("cp.async.wait_group 0;" ::: "memory");
        __syncthreads();
        if (c + 3 < kchunks) issue(c + 3, (c + 3) & 3);

        const int st = c & 3;
        const uint32_t aB = sb + st * 24576, bB = aB + 16384;
#pragma unroll
        for (int s = 0; s < 2; s++) {
            uint32_t af[4][4], bf[8][2];
            const uint32_t cc = (uint32_t)(2 * s + hs);
#pragma unroll
            for (int mt = 0; mt < 4; mt++)
                ldsm4(af[mt], aB + arow[mt] + ((cc ^ axor[mt]) << 4));
#pragma unroll
            for (int np = 0; np < 4; np++) {
                uint32_t t4[4];
                ldsm4(t4, bB + brow[np] + ((cc ^ bxor[np]) << 4));
                bf[2 * np][0] = t4[0];
                bf[2 * np][1] = t4[2];
                bf[2 * np + 1][0] = t4[1];
                bf[2 * np + 1][1] = t4[3];
            }
#pragma unroll
            for (int mt = 0; mt < 4; mt++)
#pragma unroll
                for (int nt = 0; nt < 8; nt++)
                    mma_f16(acc[mt][nt], af[mt][0], af[mt][1], af[mt][2], af[mt][3],
                            bf[nt][0], bf[nt][1]);
        }
    }

    const float* bp = bias ? bias + (long long)z2 * sbias2 : nullptr;
#pragma unroll
    for (int mt = 0; mt < 4; mt++) {
#pragma unroll
        for (int nt = 0; nt < 8; nt++) {
            int r = bm + wm + mt * 16 + g;
            int cc = bn + wn + nt * 8 + q * 2;
            float b0v = bp ? bp[cc] : 0.f;
            float b1v = bp ? bp[cc + 1] : 0.f;
            cwrite(C + (long long)r * ldc + cc,
                   alpha * acc[mt][nt][0] + b0v, alpha * acc[mt][nt][1] + b1v);
            cwrite(C + (long long)(r + 8) * ldc + cc,
                   alpha * acc[mt][nt][2] + b0v, alpha * acc[mt][nt][3] + b1v);
        }
    }
}

// ---------------- fp32 -> fp16 convert ----------------
__global__ void conv_f2h(const float* __restrict__ in, __half* __restrict__ out, int n4) {
    int i = blockIdx.x * 256 + threadIdx.x;
    if (i < n4) {
        float4 v = reinterpret_cast<const float4*>(in)[i];
        __half2 h0 = __floats2half2_rn(v.x, v.y);
        __half2 h1 = __floats2half2_rn(v.z, v.w);
        uint2 u;
        u.x = *reinterpret_cast<uint32_t*>(&h0);
        u.y = *reinterpret_cast<uint32_t*>(&h1);
        reinterpret_cast<uint2*>(out)[i] = u;
    }
}

// ---------------- per-head transpose fp32 [R,C] -> fp16 [C,R] ----------------
__global__ void trans_f2h(const float* __restrict__ in, __half* __restrict__ out,
                          int R, int C) {
    __shared__ float t[32][33];
    const float* ip = in + (size_t)blockIdx.z * R * C;
    __half* op = out + (size_t)blockIdx.z * R * C;
    int bx = blockIdx.x * 32, by = blockIdx.y * 32;
    int tx = threadIdx.x & 31, ty = threadIdx.x >> 5;
#pragma unroll
    for (int j = 0; j < 32; j += 8)
        t[ty + j][tx] = ip[(size_t)(by + ty + j) * C + bx + tx];
    __syncthreads();
#pragma unroll
    for (int j = 0; j < 32; j += 8)
        op[(size_t)(bx + ty + j) * R + by + tx] = __float2half(t[tx][ty + j]);
}

// ---------------- folded bias: cvec = bo + bv_flat @ Wo ----------------
__global__ void cvec_partial_k(const float* __restrict__ bv, const float* __restrict__ Wo) {
    int j = blockIdx.x * 256 + threadIdx.x;
    int r0 = blockIdx.y * 256;
    float acc = 0.f;
    for (int r = r0; r < r0 + 256; r++) acc += bv[r] * Wo[(size_t)r * D_ + j];
    g_cpart[blockIdx.y * D_ + j] = acc;
}
__global__ void cvec_final_k(const float* __restrict__ bo) {
    int j = blockIdx.x * 256 + threadIdx.x;
    float acc = bo[j];
    for (int r = 0; r < 32; r++) acc += g_cpart[r * D_ + j];
    g_cvec[j] = acc;
}

// ------- row softmax: fp32 scores -> fp16 P packed into the row's first half -------
__global__ __launch_bounds__(256) void softmax_k() {
    float* row = g_P + (size_t)blockIdx.x * S_;
    int tid = threadIdx.x;
    float4 u = *(const float4*)(row + tid * 8);
    float4 w = *(const float4*)(row + tid * 8 + 4);
    float v[8] = {u.x, u.y, u.z, u.w, w.x, w.y, w.z, w.w};

    float mx = -1e30f;
#pragma unroll
    for (int i = 0; i < 8; i++) mx = fmaxf(mx, v[i]);
#pragma unroll
    for (int o = 16; o > 0; o >>= 1) mx = fmaxf(mx, __shfl_xor_sync(0xffffffffu, mx, o));
    __shared__ float red[8];
    if ((tid & 31) == 0) red[tid >> 5] = mx;
    __syncthreads();
    mx = red[0];
#pragma unroll
    for (int wi = 1; wi < 8; wi++) mx = fmaxf(mx, red[wi]);

    float s = 0.f;
#pragma unroll
    for (int i = 0; i < 8; i++) {
        v[i] = exp2f((v[i] - mx) * 1.4426950408889634f);
        s += v[i];
    }
#pragma unroll
    for (int o = 16; o > 0; o >>= 1) s += __shfl_xor_sync(0xffffffffu, s, o);
    __syncthreads();
    if ((tid & 31) == 0) red[tid >> 5] = s;
    __syncthreads();
    s = 0.f;
#pragma unroll
    for (int wi = 0; wi < 8; wi++) s += red[wi];
    float inv = 1.f / s;

    __half2 p0 = __floats2half2_rn(v[0] * inv, v[1] * inv);
    __half2 p1 = __floats2half2_rn(v[2] * inv, v[3] * inv);
    __half2 p2 = __floats2half2_rn(v[4] * inv, v[5] * inv);
    __half2 p3 = __floats2half2_rn(v[6] * inv, v[7] * inv);
    uint4 o;
    o.x = *reinterpret_cast<uint32_t*>(&p0);
    o.y = *reinterpret_cast<uint32_t*>(&p1);
    o.z = *reinterpret_cast<uint32_t*>(&p2);
    o.w = *reinterpret_cast<uint32_t*>(&p3);
    *reinterpret_cast<uint4*>(reinterpret_cast<__half*>(row) + tid * 8) = o;
}

// ---------------- launch ----------------
static constexpr int BIG_SMEM = 98304;

extern "C" void kernel_launch(void* const* d_in, const int* in_sizes, int n_in,
                              void* d_out, int out_size) {
    const float* z  = (const float*)d_in[0];
    const float* y  = (const float*)d_in[1];
    const float* Wq = (const float*)d_in[2];
    const float* bq = (const float*)d_in[3];
    const float* Wk = (const float*)d_in[4];
    const float* bk = (const float*)d_in[5];
    const float* Wv = (const float*)d_in[6];
    const float* bv = (const float*)d_in[7];
    const float* Wo = (const float*)d_in[8];
    const float* bo = (const float*)d_in[9];
    float* out = (float*)d_out;

    __half *pMT, *pTWo, *pWvH, *pTWq, *pTWk, *pzh, *pyh, *pQh, *pKh, *pUT;
    float *pP, *pc;
    cudaGetSymbolAddress((void**)&pMT, g_MT);
    cudaGetSymbolAddress((void**)&pTWo, g_TWo);
    cudaGetSymbolAddress((void**)&pWvH, g_WvH);
    cudaGetSymbolAddress((void**)&pTWq, g_TWq);
    cudaGetSymbolAddress((void**)&pTWk, g_TWk);
    cudaGetSymbolAddress((void**)&pzh, g_zh);
    cudaGetSymbolAddress((void**)&pyh, g_yh);
    cudaGetSymbolAddress((void**)&pQh, g_Qh);
    cudaGetSymbolAddress((void**)&pKh, g_Kh);
    cudaGetSymbolAddress((void**)&pUT, g_UT);
    cudaGetSymbolAddress((void**)&pP, g_P);
    cudaGetSymbolAddress((void**)&pc, g_cvec);

    cudaFuncSetAttribute(nt_gemm_big<__half>,
                         cudaFuncAttributeMaxDynamicSharedMemorySize, BIG_SMEM);
    cudaFuncSetAttribute(nt_gemm_big<float>,
                         cudaFuncAttributeMaxDynamicSharedMemorySize, BIG_SMEM);

    // -- pre-pass: converts + transposes + folded bias --
    conv_f2h<<<(B_ * S_ * D_ / 4 + 255) / 256, 256>>>(z, pzh, B_ * S_ * D_ / 4);
    conv_f2h<<<(B_ * S_ * D_ / 4 + 255) / 256, 256>>>(y, pyh, B_ * S_ * D_ / 4);
    conv_f2h<<<(H_ * D_ * D_ / 4 + 255) / 256, 256>>>(Wv, pWvH, H_ * D_ * D_ / 4);
    trans_f2h<<<dim3(32, 32, 8), 256>>>(Wo, pTWo, 1024, 1024);
    trans_f2h<<<dim3(4, 32, 8), 256>>>(Wq, pTWq, 1024, 128);
    trans_f2h<<<dim3(4, 32, 8), 256>>>(Wk, pTWk, 1024, 128);
    cvec_partial_k<<<dim3(4, 32), 256>>>(bv, Wo);
    cvec_final_k<<<4, 256>>>(bo);

    // 1) M^T[h] = TWo[h] @ WvH[h]^T              [h] x (1024,1024,1024)
    nt_gemm_big<__half><<<dim3(8, 4, 8), 256, BIG_SMEM>>>(
        pTWo, pWvH, pMT, nullptr, 32, 1024, 1024, 1024,
        0, (long long)D_ * D_, 0, (long long)D_ * D_, 0, (long long)D_ * D_,
        8, 0, 1.f, 30, 0, 0);

    // 2) Q[b,h] = yh[b] @ TWq[h]^T + bq          [b,h] x (2048,128,1024)
    nt_gemm<__half><<<dim3(1, 16, 32), 256>>>(
        pyh, pTWq, pQh, bq, 32, 1024, 1024, 128,
        (long long)S_ * D_, 0, 0, (long long)KQ_ * D_,
        (long long)H_ * S_ * KQ_, (long long)S_ * KQ_, 8, 128, 1.f, 30, 0, 0);

    // 3) K[b,h] = zh[b] @ TWk[h]^T + bk
    nt_gemm<__half><<<dim3(1, 16, 32), 256>>>(
        pzh, pTWk, pKh, bk, 32, 1024, 1024, 128,
        (long long)S_ * D_, 0, 0, (long long)KQ_ * D_,
        (long long)H_ * S_ * KQ_, (long long)S_ * KQ_, 8, 128, 1.f, 30, 0, 0);

    // 4) U^T[b,h] = MT[h] @ zh[b]^T              [b,h] x (1024,2048,1024)
    nt_gemm_big<__half><<<dim3(16, 4, 32), 256, BIG_SMEM>>>(
        pMT, pzh, pUT, nullptr, 32, 1024, 1024, 2048,
        0, (long long)D_ * D_, (long long)S_ * D_, 0,
        (long long)H_ * D_ * S_, (long long)D_ * S_, 8, 0, 1.f, 30, 0, 0);

    // 5) scores = (Qh @ Kh^T) / sqrt(128)        [b,h] x (2048,2048,128), fp32 out
    nt_gemm<float><<<dim3(16, 16, 32), 256>>>(
        pQh, pKh, pP, nullptr, 4, 128, 128, 2048,
        (long long)H_ * S_ * KQ_, (long long)S_ * KQ_,
        (long long)H_ * S_ * KQ_, (long long)S_ * KQ_,
        (long long)H_ * S_ * S_, (long long)S_ * S_,
        8, 0, 0.08838834764831845f, 30, 0, 0);

    // 6) softmax rows (fp32 -> fp16 packed)
    softmax_k<<<B_ * H_ * S_, 256>>>();

    // 7) out = sum_h P_h @ UT_h^T + cvec         [b] x (2048,1024,K=8*2048) head-fused
    nt_gemm_big<float><<<dim3(8, 8, 4), 256, BIG_SMEM>>>(
        (const __half*)pP, pUT, out, pc, 512, 2 * S_, 2048, 1024,
        0, (long long)H_ * S_ * 2 * S_, 0, (long long)H_ * D_ * S_,
        0, (long long)S_ * D_, 4, 0, 1.f,
        6, (long long)S_ * 2 * S_, (long long)D_ * S_);
}

// round 8
// speedup vs baseline: 1.0332x; 1.0332x over previous
#include <cuda_runtime.h>
#include <cuda_fp16.h>
#include <cstdint>

#define DI __device__ __forceinline__

static constexpr int B_ = 4, H_ = 8, S_ = 2048, D_ = 1024, KQ_ = 128;
static constexpr int PGRID = 296;   // 148 SMs x 2 CTAs (sm_100a B200)

// ---------------- scratch (device globals; no allocations allowed) ----------------
__device__ __half g_MT[(size_t)H_ * D_ * D_];    //  16 MB  M^T[h][j][d]
__device__ __half g_TWo[(size_t)H_ * D_ * D_];   //  16 MB  Wo^T per head [h][j][v]
__device__ __half g_WvH[(size_t)H_ * D_ * D_];   //  16 MB  Wv fp16 [h][d][v]
__device__ __half g_TWq[(size_t)H_ * KQ_ * D_];  //   2 MB  Wq^T [h][kq][d]
__device__ __half g_TWk[(size_t)H_ * KQ_ * D_];  //   2 MB
__device__ __half g_zh[(size_t)B_ * S_ * D_];    //  16 MB
__device__ __half g_yh[(size_t)B_ * S_ * D_];    //  16 MB
__device__ __half g_Qh[(size_t)B_ * H_ * S_ * KQ_];  // 16 MB
__device__ __half g_Kh[(size_t)B_ * H_ * S_ * KQ_];  // 16 MB
__device__ __half g_UT[(size_t)B_ * H_ * D_ * S_];   // 128 MB U^T[b,h][j][t]
__device__ __half g_Ph[(size_t)B_ * H_ * S_ * S_];   // 256 MB scores / P fp16
__device__ float g_cvec[D_];
__device__ float g_cpart[32 * D_];

// ---------------- helpers ----------------
DI uint32_t smem_u32(const void* p) {
    uint32_t a;
    asm("{ .reg .u64 t; cvta.to.shared.u64 t, %1; cvt.u32.u64 %0, t; }" : "=r"(a) : "l"(p));
    return a;
}
DI void mma_f16(float c[4], uint32_t a0, uint32_t a1, uint32_t a2, uint32_t a3,
                uint32_t b0, uint32_t b1) {
    asm volatile(
        "mma.sync.aligned.m16n8k16.row.col.f32.f16.f16.f32 "
        "{%0,%1,%2,%3}, {%4,%5,%6,%7}, {%8,%9}, {%0,%1,%2,%3};"
        : "+f"(c[0]), "+f"(c[1]), "+f"(c[2]), "+f"(c[3])
        : "r"(a0), "r"(a1), "r"(a2), "r"(a3), "r"(b0), "r"(b1));
}
DI void ldsm4(uint32_t r[4], uint32_t a) {
    asm volatile("ldmatrix.sync.aligned.m8n8.x4.shared.b16 {%0,%1,%2,%3}, [%4];"
                 : "=r"(r[0]), "=r"(r[1]), "=r"(r[2]), "=r"(r[3]) : "r"(a));
}
DI void cp16(uint32_t d, const void* s) {
    asm volatile("cp.async.cg.shared.global [%0], [%1], 16;" :: "r"(d), "l"(s));
}
DI void cp_commit() { asm volatile("cp.async.commit_group;" ::: "memory"); }

DI void cwrite(__half* p, float a, float b) {
    *reinterpret_cast<__half2*>(p) = __floats2half2_rn(a, b);
}
DI void cwrite(float* p, float a, float b) {
    *reinterpret_cast<float2*>(p) = make_float2(a, b);
}

// =============== fp16 NT GEMM, 128x128 CTA, 3-stage cp.async, PERSISTENT ===============
// C = alpha * A @ B^T + bias.  A [M,K] fp16, B [N,K] fp16, C fp16 or fp32.
// tile index -> (tx, ty, tz): tz = tile/(ngx*ngy); z1 = tz/Z2, z2 = tz%Z2.
// head-fused K: chunk c -> h = c>>hshift (offset h*s?h), k-off (c&hmask)*32.
template <typename CT>
__global__ __launch_bounds__(256, 2) void nt_gemm(
    const __half* __restrict__ Ag, const __half* __restrict__ Bg,
    CT* __restrict__ Cg, const float* __restrict__ bias,
    int kchunks, int lda, int ldb, int ldc,
    long long sA1, long long sA2, long long sB1, long long sB2,
    long long sC1, long long sC2, int Z2, int sbias2, float alpha,
    int hshift, long long sAh, long long sBh,
    int ngx, int ngy, int ntiles)
{
    __shared__ __align__(128) uint32_t sAs[3][2048];
    __shared__ __align__(128) uint32_t sBs[3][2048];

    const int tid = threadIdx.x, lane = tid & 31, wid = tid >> 5;
    const int wm = (wid & 1) * 64, wn = (wid >> 1) * 32;
    const int g = lane >> 2, q = lane & 3;

    int lr[2], lc[2];
    uint32_t dst[2];
#pragma unroll
    for (int i = 0; i < 2; i++) {
        int qid = tid + i * 256;
        lr[i] = qid >> 2;
        lc[i] = qid & 3;
        dst[i] = (uint32_t)((lr[i] * 4 + (lc[i] ^ ((lr[i] >> 1) & 3))) << 4);
    }

    const uint32_t sAb = smem_u32(&sAs[0][0]);
    const uint32_t sBb = smem_u32(&sBs[0][0]);

    const int l15 = lane & 15, hs = lane >> 4;
    uint32_t arow[4], axor[4], brow[2], bxor[2];
#pragma unroll
    for (int mt = 0; mt < 4; mt++) {
        int rr = wm + mt * 16 + l15;
        arow[mt] = (uint32_t)(rr * 64);
        axor[mt] = (uint32_t)((rr >> 1) & 3);
    }
#pragma unroll
    for (int np = 0; np < 2; np++) {
        int nn = wn + np * 16 + l15;
        brow[np] = (uint32_t)(nn * 64);
        bxor[np] = (uint32_t)((nn >> 1) & 3);
    }

    const int hmask = (hshift < 30) ? ((1 << hshift) - 1) : 0x3FFFFFFF;
    const int nxy = ngx * ngy;

    for (int tile = blockIdx.x; tile < ntiles; tile += gridDim.x) {
        const int tz = tile / nxy, rxy = tile - tz * nxy;
        const int tyv = rxy / ngx, txv = rxy - tyv * ngx;
        const int z1 = tz / Z2, z2 = tz - z1 * Z2;
        const __half* A = Ag + z1 * sA1 + z2 * sA2;
        const __half* Bp = Bg + z1 * sB1 + z2 * sB2;
        CT* C = Cg + z1 * sC1 + z2 * sC2;
        const int bm = tyv * 128, bn = txv * 128;

        long long aoff[2], boff[2];
#pragma unroll
        for (int i = 0; i < 2; i++) {
            aoff[i] = (long long)(bm + lr[i]) * lda + lc[i] * 8;
            boff[i] = (long long)(bn + lr[i]) * ldb + lc[i] * 8;
        }

        float acc[4][4][4];
#pragma unroll
        for (int i = 0; i < 4; i++)
#pragma unroll
            for (int j = 0; j < 4; j++)
#pragma unroll
                for (int k = 0; k < 4; k++) acc[i][j][k] = 0.f;

        auto issue = [&](int c, int st) {
            const __half* Ac = A + (long long)(c >> hshift) * sAh + (c & hmask) * 32;
            const __half* Bc = Bp + (long long)(c >> hshift) * sBh + (c & hmask) * 32;
            const uint32_t a0 = sAb + st * 8192, b0 = sBb + st * 8192;
#pragma unroll
            for (int i = 0; i < 2; i++) {
                cp16(a0 + dst[i], Ac + aoff[i]);
                cp16(b0 + dst[i], Bc + boff[i]);
            }
            cp_commit();
        };

        issue(0, 0);
        if (kchunks > 1) issue(1, 1);

        for (int c = 0; c < kchunks; c++) {
            if (c + 1 < kchunks)
                asm volatile("cp.async.wait_group 1;" ::: "memory");
            else
                asm volatile("cp.async.wait_group 0;" ::: "memory");
            __syncthreads();
            if (c + 2 < kchunks) issue(c + 2, (c + 2) % 3);

            const int st = c % 3;
            const uint32_t aB = sAb + st * 8192, bB = sBb + st * 8192;
#pragma unroll
            for (int s = 0; s < 2; s++) {
                uint32_t af[4][4], bf[4][2];
                const uint32_t cc = (uint32_t)(2 * s + hs);
#pragma unroll
                for (int mt = 0; mt < 4; mt++)
                    ldsm4(af[mt], aB + arow[mt] + ((cc ^ axor[mt]) << 4));
#pragma unroll
                for (int np = 0; np < 2; np++) {
                    uint32_t t4[4];
                    ldsm4(t4, bB + brow[np] + ((cc ^ bxor[np]) << 4));
                    bf[2 * np][0] = t4[0];
                    bf[2 * np][1] = t4[2];
                    bf[2 * np + 1][0] = t4[1];
                    bf[2 * np + 1][1] = t4[3];
                }
#pragma unroll
                for (int mt = 0; mt < 4; mt++)
#pragma unroll
                    for (int nt = 0; nt < 4; nt++)
                        mma_f16(acc[mt][nt], af[mt][0], af[mt][1], af[mt][2], af[mt][3],
                                bf[nt][0], bf[nt][1]);
            }
        }

        const float* bp = bias ? bias + (long long)z2 * sbias2 : nullptr;
#pragma unroll
        for (int mt = 0; mt < 4; mt++) {
#pragma unroll
            for (int nt = 0; nt < 4; nt++) {
                int r = bm + wm + mt * 16 + g;
                int cc = bn + wn + nt * 8 + q * 2;
                float b0v = bp ? bp[cc] : 0.f;
                float b1v = bp ? bp[cc + 1] : 0.f;
                cwrite(C + (long long)r * ldc + cc,
                       alpha * acc[mt][nt][0] + b0v, alpha * acc[mt][nt][1] + b1v);
                cwrite(C + (long long)(r + 8) * ldc + cc,
                       alpha * acc[mt][nt][2] + b0v, alpha * acc[mt][nt][3] + b1v);
            }
        }
        __syncthreads();   // protect smem stages before next tile re-primes
    }
}

// ---------------- fp32 -> fp16 convert ----------------
__global__ void conv_f2h(const float* __restrict__ in, __half* __restrict__ out, int n4) {
    int i = blockIdx.x * 256 + threadIdx.x;
    if (i < n4) {
        float4 v = reinterpret_cast<const float4*>(in)[i];
        __half2 h0 = __floats2half2_rn(v.x, v.y);
        __half2 h1 = __floats2half2_rn(v.z, v.w);
        uint2 u;
        u.x = *reinterpret_cast<uint32_t*>(&h0);
        u.y = *reinterpret_cast<uint32_t*>(&h1);
        reinterpret_cast<uint2*>(out)[i] = u;
    }
}

// ---------------- per-head transpose fp32 [R,C] -> fp16 [C,R] ----------------
__global__ void trans_f2h(const float* __restrict__ in, __half* __restrict__ out,
                          int R, int C) {
    __shared__ float t[32][33];
    const float* ip = in + (size_t)blockIdx.z * R * C;
    __half* op = out + (size_t)blockIdx.z * R * C;
    int bx = blockIdx.x * 32, by = blockIdx.y * 32;
    int tx = threadIdx.x & 31, ty = threadIdx.x >> 5;
#pragma unroll
    for (int j = 0; j < 32; j += 8)
        t[ty + j][tx] = ip[(size_t)(by + ty + j) * C + bx + tx];
    __syncthreads();
#pragma unroll
    for (int j = 0; j < 32; j += 8)
        op[(size_t)(bx + ty + j) * R + by + tx] = __float2half(t[tx][ty + j]);
}

// ---------------- folded bias: cvec = bo + bv_flat @ Wo ----------------
__global__ void cvec_partial_k(const float* __restrict__ bv, const float* __restrict__ Wo) {
    int j = blockIdx.x * 256 + threadIdx.x;
    int r0 = blockIdx.y * 256;
    float acc = 0.f;
    for (int r = r0; r < r0 + 256; r++) acc += bv[r] * Wo[(size_t)r * D_ + j];
    g_cpart[blockIdx.y * D_ + j] = acc;
}
__global__ void cvec_final_k(const float* __restrict__ bo) {
    int j = blockIdx.x * 256 + threadIdx.x;
    float acc = bo[j];
    for (int r = 0; r < 32; r++) acc += g_cpart[r * D_ + j];
    g_cvec[j] = acc;
}

// ------- row softmax on fp16 scores, in place -------
__global__ __launch_bounds__(256) void softmax_k() {
    __half* row = g_Ph + (size_t)blockIdx.x * S_;
    int tid = threadIdx.x;
    uint4 u = *reinterpret_cast<const uint4*>(row + tid * 8);
    float v[8];
    {
        __half2* hp = reinterpret_cast<__half2*>(&u);
#pragma unroll
        for (int i = 0; i < 4; i++) {
            float2 f = __half22float2(hp[i]);
            v[2 * i] = f.x;
            v[2 * i + 1] = f.y;
        }
    }

    float mx = -1e30f;
#pragma unroll
    for (int i = 0; i < 8; i++) mx = fmaxf(mx, v[i]);
#pragma unroll
    for (int o = 16; o > 0; o >>= 1) mx = fmaxf(mx, __shfl_xor_sync(0xffffffffu, mx, o));
    __shared__ float red[8];
    if ((tid & 31) == 0) red[tid >> 5] = mx;
    __syncthreads();
    mx = red[0];
#pragma unroll
    for (int wi = 1; wi < 8; wi++) mx = fmaxf(mx, red[wi]);

    float s = 0.f;
#pragma unroll
    for (int i = 0; i < 8; i++) {
        v[i] = exp2f((v[i] - mx) * 1.4426950408889634f);
        s += v[i];
    }
#pragma unroll
    for (int o = 16; o > 0; o >>= 1) s += __shfl_xor_sync(0xffffffffu, s, o);
    __syncthreads();
    if ((tid & 31) == 0) red[tid >> 5] = s;
    __syncthreads();
    s = 0.f;
#pragma unroll
    for (int wi = 0; wi < 8; wi++) s += red[wi];
    float inv = 1.f / s;

    __half2 p0 = __floats2half2_rn(v[0] * inv, v[1] * inv);
    __half2 p1 = __floats2half2_rn(v[2] * inv, v[3] * inv);
    __half2 p2 = __floats2half2_rn(v[4] * inv, v[5] * inv);
    __half2 p3 = __floats2half2_rn(v[6] * inv, v[7] * inv);
    uint4 o;
    o.x = *reinterpret_cast<uint32_t*>(&p0);
    o.y = *reinterpret_cast<uint32_t*>(&p1);
    o.z = *reinterpret_cast<uint32_t*>(&p2);
    o.w = *reinterpret_cast<uint32_t*>(&p3);
    *reinterpret_cast<uint4*>(row + tid * 8) = o;
}

// ---------------- launch ----------------
extern "C" void kernel_launch(void* const* d_in, const int* in_sizes, int n_in,
                              void* d_out, int out_size) {
    const float* z  = (const float*)d_in[0];
    const float* y  = (const float*)d_in[1];
    const float* Wq = (const float*)d_in[2];
    const float* bq = (const float*)d_in[3];
    const float* Wk = (const float*)d_in[4];
    const float* bk = (const float*)d_in[5];
    const float* Wv = (const float*)d_in[6];
    const float* bv = (const float*)d_in[7];
    const float* Wo = (const float*)d_in[8];
    const float* bo = (const float*)d_in[9];
    float* out = (float*)d_out;

    __half *pMT, *pTWo, *pWvH, *pTWq, *pTWk, *pzh, *pyh, *pQh, *pKh, *pUT, *pPh;
    float *pc;
    cudaGetSymbolAddress((void**)&pMT, g_MT);
    cudaGetSymbolAddress((void**)&pTWo, g_TWo);
    cudaGetSymbolAddress((void**)&pWvH, g_WvH);
    cudaGetSymbolAddress((void**)&pTWq, g_TWq);
    cudaGetSymbolAddress((void**)&pTWk, g_TWk);
    cudaGetSymbolAddress((void**)&pzh, g_zh);
    cudaGetSymbolAddress((void**)&pyh, g_yh);
    cudaGetSymbolAddress((void**)&pQh, g_Qh);
    cudaGetSymbolAddress((void**)&pKh, g_Kh);
    cudaGetSymbolAddress((void**)&pUT, g_UT);
    cudaGetSymbolAddress((void**)&pPh, g_Ph);
    cudaGetSymbolAddress((void**)&pc, g_cvec);

    // -- pre-pass: converts + transposes + folded bias --
    conv_f2h<<<(B_ * S_ * D_ / 4 + 255) / 256, 256>>>(z, pzh, B_ * S_ * D_ / 4);
    conv_f2h<<<(B_ * S_ * D_ / 4 + 255) / 256, 256>>>(y, pyh, B_ * S_ * D_ / 4);
    conv_f2h<<<(H_ * D_ * D_ / 4 + 255) / 256, 256>>>(Wv, pWvH, H_ * D_ * D_ / 4);
    trans_f2h<<<dim3(32, 32, 8), 256>>>(Wo, pTWo, 1024, 1024);
    trans_f2h<<<dim3(4, 32, 8), 256>>>(Wq, pTWq, 1024, 128);
    trans_f2h<<<dim3(4, 32, 8), 256>>>(Wk, pTWk, 1024, 128);
    cvec_partial_k<<<dim3(4, 32), 256>>>(bv, Wo);
    cvec_final_k<<<4, 256>>>(bo);

    // 1) M^T[h] = TWo[h] @ WvH[h]^T              512 tiles (8n x 8m x 8h)
    nt_gemm<__half><<<PGRID, 256>>>(
        pTWo, pWvH, pMT, nullptr, 32, 1024, 1024, 1024,
        0, (long long)D_ * D_, 0, (long long)D_ * D_, 0, (long long)D_ * D_,
        8, 0, 1.f, 30, 0, 0, 8, 8, 512);

    // 2) Q[b,h] = yh[b] @ TWq[h]^T + bq          512 tiles (1 x 16 x 32)
    nt_gemm<__half><<<PGRID, 256>>>(
        pyh, pTWq, pQh, bq, 32, 1024, 1024, 128,
        (long long)S_ * D_, 0, 0, (long long)KQ_ * D_,
        (long long)H_ * S_ * KQ_, (long long)S_ * KQ_, 8, 128, 1.f, 30, 0, 0,
        1, 16, 512);

    // 3) K[b,h] = zh[b] @ TWk[h]^T + bk
    nt_gemm<__half><<<PGRID, 256>>>(
        pzh, pTWk, pKh, bk, 32, 1024, 1024, 128,
        (long long)S_ * D_, 0, 0, (long long)KQ_ * D_,
        (long long)H_ * S_ * KQ_, (long long)S_ * KQ_, 8, 128, 1.f, 30, 0, 0,
        1, 16, 512);

    // 4) U^T[b,h] = MT[h] @ zh[b]^T              4096 tiles (16 x 8 x 32)
    nt_gemm<__half><<<PGRID, 256>>>(
        pMT, pzh, pUT, nullptr, 32, 1024, 1024, 2048,
        0, (long long)D_ * D_, (long long)S_ * D_, 0,
        (long long)H_ * D_ * S_, (long long)D_ * S_, 8, 0, 1.f, 30, 0, 0,
        16, 8, 4096);

    // 5) scores = (Qh @ Kh^T)/sqrt(128), fp16    8192 tiles (16 x 16 x 32)
    nt_gemm<__half><<<PGRID, 256>>>(
        pQh, pKh, pPh, nullptr, 4, 128, 128, 2048,
        (long long)H_ * S_ * KQ_, (long long)S_ * KQ_,
        (long long)H_ * S_ * KQ_, (long long)S_ * KQ_,
        (long long)H_ * S_ * S_, (long long)S_ * S_,
        8, 0, 0.08838834764831845f, 30, 0, 0, 16, 16, 8192);

    // 6) softmax rows (fp16 in place)
    softmax_k<<<B_ * H_ * S_, 256>>>();

    // 7) out = sum_h P_h @ UT_h^T + cvec         512 tiles (8 x 16 x 4), K=8*2048
    nt_gemm<float><<<PGRID, 256>>>(
        pPh, pUT, out, pc, 512, 2048, 2048, 1024,
        0, (long long)H_ * S_ * S_, 0, (long long)H_ * D_ * S_,
        0, (long long)S_ * D_, 4, 0, 1.f,
        6, (long long)S_ * S_, (long long)D_ * S_, 8, 16, 512);
}

// round 10
// speedup vs baseline: 1.0939x; 1.0587x over previous
#include <cuda_runtime.h>
#include <cuda_fp16.h>
#include <cstdint>

#define DI __device__ __forceinline__

static constexpr int B_ = 4, H_ = 8, S_ = 2048, D_ = 1024, KQ_ = 128;
static constexpr int PGRID = 296;   // 148 SMs x 2 CTAs

// ---------------- scratch (device globals; no allocations allowed) ----------------
__device__ __half g_MT[(size_t)H_ * D_ * D_];
__device__ __half g_TWo[(size_t)H_ * D_ * D_];
__device__ __half g_WvH[(size_t)H_ * D_ * D_];
__device__ __half g_TWq[(size_t)H_ * KQ_ * D_];
__device__ __half g_TWk[(size_t)H_ * KQ_ * D_];
__device__ __half g_zh[(size_t)B_ * S_ * D_];
__device__ __half g_yh[(size_t)B_ * S_ * D_];
__device__ __half g_Qh[(size_t)B_ * H_ * S_ * KQ_];
__device__ __half g_Kh[(size_t)B_ * H_ * S_ * KQ_];
__device__ __half g_UT[(size_t)B_ * H_ * D_ * S_];   // U^T[b,h][j][t]
__device__ __half g_Ph[(size_t)B_ * H_ * S_ * S_];   // scores / P fp16
__device__ float g_cvec[D_];
__device__ float g_cpart[32 * D_];

// ---------------- helpers ----------------
DI uint32_t smem_u32(const void* p) {
    uint32_t a;
    asm("{ .reg .u64 t; cvta.to.shared.u64 t, %1; cvt.u32.u64 %0, t; }" : "=r"(a) : "l"(p));
    return a;
}
DI void mma_f16(float c[4], uint32_t a0, uint32_t a1, uint32_t a2, uint32_t a3,
                uint32_t b0, uint32_t b1) {
    asm volatile(
        "mma.sync.aligned.m16n8k16.row.col.f32.f16.f16.f32 "
        "{%0,%1,%2,%3}, {%4,%5,%6,%7}, {%8,%9}, {%0,%1,%2,%3};"
        : "+f"(c[0]), "+f"(c[1]), "+f"(c[2]), "+f"(c[3])
        : "r"(a0), "r"(a1), "r"(a2), "r"(a3), "r"(b0), "r"(b1));
}
DI void ldsm4(uint32_t r[4], uint32_t a) {
    asm volatile("ldmatrix.sync.aligned.m8n8.x4.shared.b16 {%0,%1,%2,%3}, [%4];"
                 : "=r"(r[0]), "=r"(r[1]), "=r"(r[2]), "=r"(r[3]) : "r"(a));
}
DI void cp16(uint32_t d, const void* s) {
    asm volatile("cp.async.cg.shared.global [%0], [%1], 16;" :: "r"(d), "l"(s));
}
DI void cp_commit() { asm volatile("cp.async.commit_group;" ::: "memory"); }

DI void cwrite(__half* p, float a, float b) {
    *reinterpret_cast<__half2*>(p) = __floats2half2_rn(a, b);
}
DI void cwrite(float* p, float a, float b) {
    *reinterpret_cast<float2*>(p) = make_float2(a, b);
}

// ====== fp16 NT GEMM, 128x128 CTA, K-chunk 64 halves, 3-stage cp.async, persistent ======
// C = alpha * A @ B^T + bias.  A [M,K], B [N,K] fp16 row-major; C fp16/fp32.
// SMEM tile/stage: 128 rows x 64 halves (128B row); 16B chunk (r,c∈0..7) at
// p = r*8 + (c ^ (r&7)).  Stage = 32KB (A 16KB + B 16KB), 3 stages = 96KB dyn.
// tile -> (tx,ty,tz): tz = tile/(ngx*ngy); z1=tz/Z2, z2=tz%Z2.
// head-fused K: chunk c -> h = c>>hshift (offset h*s?h), k-off (c&hmask)*64.
template <typename CT>
__global__ __launch_bounds__(256, 2) void nt_gemm(
    const __half* __restrict__ Ag, const __half* __restrict__ Bg,
    CT* __restrict__ Cg, const float* __restrict__ bias,
    int kchunks, int lda, int ldb, int ldc,
    long long sA1, long long sA2, long long sB1, long long sB2,
    long long sC1, long long sC2, int Z2, int sbias2, float alpha,
    int hshift, long long sAh, long long sBh,
    int ngx, int ngy, int ntiles)
{
    extern __shared__ __align__(128) uint32_t dyn_smem[];
    const uint32_t sb = smem_u32(dyn_smem);

    const int tid = threadIdx.x, lane = tid & 31, wid = tid >> 5;
    const int wm = (wid & 1) * 64, wn = (wid >> 1) * 32;
    const int g = lane >> 2, q = lane & 3;

    int lr[4], lc[4];
    uint32_t dst[4];
#pragma unroll
    for (int i = 0; i < 4; i++) {
        int qid = tid + i * 256;
        lr[i] = qid >> 3;
        lc[i] = qid & 7;
        dst[i] = (uint32_t)((lr[i] * 8 + (lc[i] ^ (lr[i] & 7))) << 4);
    }

    const int l15 = lane & 15, hs = lane >> 4;
    uint32_t arow[4], axor[4], brow[2], bxor[2];
#pragma unroll
    for (int mt = 0; mt < 4; mt++) {
        int rr = wm + mt * 16 + l15;
        arow[mt] = (uint32_t)(rr * 128);
        axor[mt] = (uint32_t)(rr & 7);
    }
#pragma unroll
    for (int np = 0; np < 2; np++) {
        int nn = wn + np * 16 + l15;
        brow[np] = (uint32_t)(nn * 128);
        bxor[np] = (uint32_t)(nn & 7);
    }

    const int hmask = (hshift < 30) ? ((1 << hshift) - 1) : 0x3FFFFFFF;
    const int nxy = ngx * ngy;

    for (int tile = blockIdx.x; tile < ntiles; tile += gridDim.x) {
        const int tz = tile / nxy, rxy = tile - tz * nxy;
        const int tyv = rxy / ngx, txv = rxy - tyv * ngx;
        const int z1 = tz / Z2, z2 = tz - z1 * Z2;
        const __half* A = Ag + z1 * sA1 + z2 * sA2;
        const __half* Bp = Bg + z1 * sB1 + z2 * sB2;
        CT* C = Cg + z1 * sC1 + z2 * sC2;
        const int bm = tyv * 128, bn = txv * 128;

        long long aoff[4], boff[4];
#pragma unroll
        for (int i = 0; i < 4; i++) {
            aoff[i] = (long long)(bm + lr[i]) * lda + lc[i] * 8;
            boff[i] = (long long)(bn + lr[i]) * ldb + lc[i] * 8;
        }

        float acc[4][4][4];
#pragma unroll
        for (int i = 0; i < 4; i++)
#pragma unroll
            for (int j = 0; j < 4; j++)
#pragma unroll
                for (int k = 0; k < 4; k++) acc[i][j][k] = 0.f;

        auto issue = [&](int c, int st) {
            const __half* Ac = A + (long long)(c >> hshift) * sAh + (c & hmask) * 64;
            const __half* Bc = Bp + (long long)(c >> hshift) * sBh + (c & hmask) * 64;
            const uint32_t a0 = sb + st * 32768, b0 = a0 + 16384;
#pragma unroll
            for (int i = 0; i < 4; i++) {
                cp16(a0 + dst[i], Ac + aoff[i]);
                cp16(b0 + dst[i], Bc + boff[i]);
            }
            cp_commit();
        };

        issue(0, 0);
        if (kchunks > 1) issue(1, 1);

        for (int c = 0; c < kchunks; c++) {
            if (c + 1 < kchunks)
                asm volatile("cp.async.wait_group 1;" ::: "memory");
            else
                asm volatile("cp.async.wait_group 0;" ::: "memory");
            __syncthreads();
            if (c + 2 < kchunks) issue(c + 2, (c + 2) % 3);

            const int st = c % 3;
            const uint32_t aB = sb + st * 32768, bB = aB + 16384;
#pragma unroll
            for (int s = 0; s < 4; s++) {
                uint32_t af[4][4], bf[4][2];
                const uint32_t cc = (uint32_t)(2 * s + hs);
#pragma unroll
                for (int mt = 0; mt < 4; mt++)
                    ldsm4(af[mt], aB + arow[mt] + ((cc ^ axor[mt]) << 4));
#pragma unroll
                for (int np = 0; np < 2; np++) {
                    uint32_t t4[4];
                    ldsm4(t4, bB + brow[np] + ((cc ^ bxor[np]) << 4));
                    bf[2 * np][0] = t4[0];
                    bf[2 * np][1] = t4[2];
                    bf[2 * np + 1][0] = t4[1];
                    bf[2 * np + 1][1] = t4[3];
                }
#pragma unroll
                for (int mt = 0; mt < 4; mt++)
#pragma unroll
                    for (int nt = 0; nt < 4; nt++)
                        mma_f16(acc[mt][nt], af[mt][0], af[mt][1], af[mt][2], af[mt][3],
                                bf[nt][0], bf[nt][1]);
            }
        }

        const float* bp = bias ? bias + (long long)z2 * sbias2 : nullptr;
#pragma unroll
        for (int mt = 0; mt < 4; mt++) {
#pragma unroll
            for (int nt = 0; nt < 4; nt++) {
                int r = bm + wm + mt * 16 + g;
                int cc = bn + wn + nt * 8 + q * 2;
                float b0v = bp ? bp[cc] : 0.f;
                float b1v = bp ? bp[cc + 1] : 0.f;
                cwrite(C + (long long)r * ldc + cc,
                       alpha * acc[mt][nt][0] + b0v, alpha * acc[mt][nt][1] + b1v);
                cwrite(C + (long long)(r + 8) * ldc + cc,
                       alpha * acc[mt][nt][2] + b0v, alpha * acc[mt][nt][3] + b1v);
            }
        }
        __syncthreads();
    }
}

// ============ fused prepass: converts + transposes + cvec partial (one kernel) ============
// segments by blockIdx.x:
//  [0,8192)        conv z      [8192,16384)  conv y      [16384,24576) conv Wv
//  [24576,32768)   trans Wo    [32768,33792) trans Wq    [33792,34816) trans Wk
//  [34816,34944)   cvec_partial
__global__ __launch_bounds__(256) void prepass_k(
    const float* __restrict__ z, const float* __restrict__ y,
    const float* __restrict__ Wv, const float* __restrict__ Wo,
    const float* __restrict__ Wq, const float* __restrict__ Wk,
    const float* __restrict__ bv)
{
    __shared__ float t[32][33];
    const int b = blockIdx.x, tid = threadIdx.x;

    if (b < 24576) {
        const float* in;
        __half* out;
        int i;
        if (b < 8192)       { in = z;  out = g_zh;  i = b * 256 + tid; }
        else if (b < 16384) { in = y;  out = g_yh;  i = (b - 8192) * 256 + tid; }
        else                { in = Wv; out = g_WvH; i = (b - 16384) * 256 + tid; }
        float4 v = reinterpret_cast<const float4*>(in)[i];
        __half2 h0 = __floats2half2_rn(v.x, v.y);
        __half2 h1 = __floats2half2_rn(v.z, v.w);
        uint2 u;
        u.x = *reinterpret_cast<uint32_t*>(&h0);
        u.y = *reinterpret_cast<uint32_t*>(&h1);
        reinterpret_cast<uint2*>(out)[i] = u;
        return;
    }
    if (b < 34816) {
        const float* in;
        __half* out;
        int R, C, idx;
        if (b < 32768)      { in = Wo; out = g_TWo; R = 1024; C = 1024; idx = b - 24576; }
        else if (b < 33792) { in = Wq; out = g_TWq; R = 1024; C = 128;  idx = b - 32768; }
        else                { in = Wk; out = g_TWk; R = 1024; C = 128;  idx = b - 33792; }
        const int ngx = C / 32;
        const int h = idx / (ngx * 32);
        const int rxy = idx - h * (ngx * 32);
        const int byi = rxy / ngx, bxi = rxy - byi * ngx;
        const float* ip = in + (size_t)h * R * C;
        __half* op = out + (size_t)h * R * C;
        int bx = bxi * 32, by = byi * 32;
        int tx = tid & 31, ty = tid >> 5;
#pragma unroll
        for (int j = 0; j < 32; j += 8)
            t[ty + j][tx] = ip[(size_t)(by + ty + j) * C + bx + tx];
        __syncthreads();
#pragma unroll
        for (int j = 0; j < 32; j += 8)
            op[(size_t)(bx + ty + j) * R + by + tx] = __float2half(t[tx][ty + j]);
        return;
    }
    {
        const int idx = b - 34816;          // 0..127  (4 j-blocks x 32 r-blocks)
        const int j = (idx & 3) * 256 + tid;
        const int r0 = (idx >> 2) * 256;
        float acc = 0.f;
        for (int r = r0; r < r0 + 256; r++) acc += bv[r] * Wo[(size_t)r * D_ + j];
        g_cpart[(idx >> 2) * D_ + j] = acc;
    }
}

__global__ void cvec_final_k(const float* __restrict__ bo) {
    int j = blockIdx.x * 256 + threadIdx.x;
    float acc = bo[j];
    for (int r = 0; r < 32; r++) acc += g_cpart[r * D_ + j];
    g_cvec[j] = acc;
}

// ------- row softmax on fp16 scores, in place -------
__global__ __launch_bounds__(256) void softmax_k() {
    __half* row = g_Ph + (size_t)blockIdx.x * S_;
    int tid = threadIdx.x;
    uint4 u = *reinterpret_cast<const uint4*>(row + tid * 8);
    float v[8];
    {
        __half2* hp = reinterpret_cast<__half2*>(&u);
#pragma unroll
        for (int i = 0; i < 4; i++) {
            float2 f = __half22float2(hp[i]);
            v[2 * i] = f.x;
            v[2 * i + 1] = f.y;
        }
    }
    float mx = -1e30f;
#pragma unroll
    for (int i = 0; i < 8; i++) mx = fmaxf(mx, v[i]);
#pragma unroll
    for (int o = 16; o > 0; o >>= 1) mx = fmaxf(mx, __shfl_xor_sync(0xffffffffu, mx, o));
    __shared__ float red[8];
    if ((tid & 31) == 0) red[tid >> 5] = mx;
    __syncthreads();
    mx = red[0];
#pragma unroll
    for (int wi = 1; wi < 8; wi++) mx = fmaxf(mx, red[wi]);

    float s = 0.f;
#pragma unroll
    for (int i = 0; i < 8; i++) {
        v[i] = exp2f((v[i] - mx) * 1.4426950408889634f);
        s += v[i];
    }
#pragma unroll
    for (int o = 16; o > 0; o >>= 1) s += __shfl_xor_sync(0xffffffffu, s, o);
    __syncthreads();
    if ((tid & 31) == 0) red[tid >> 5] = s;
    __syncthreads();
    s = 0.f;
#pragma unroll
    for (int wi = 0; wi < 8; wi++) s += red[wi];
    float inv = 1.f / s;

    __half2 p0 = __floats2half2_rn(v[0] * inv, v[1] * inv);
    __half2 p1 = __floats2half2_rn(v[2] * inv, v[3] * inv);
    __half2 p2 = __floats2half2_rn(v[4] * inv, v[5] * inv);
    __half2 p3 = __floats2half2_rn(v[6] * inv, v[7] * inv);
    uint4 o;
    o.x = *reinterpret_cast<uint32_t*>(&p0);
    o.y = *reinterpret_cast<uint32_t*>(&p1);
    o.z = *reinterpret_cast<uint32_t*>(&p2);
    o.w = *reinterpret_cast<uint32_t*>(&p3);
    *reinterpret_cast<uint4*>(row + tid * 8) = o;
}

// ---------------- launch ----------------
static constexpr int GSMEM = 98304;   // 3 stages x 32KB

extern "C" void kernel_launch(void* const* d_in, const int* in_sizes, int n_in,
                              void* d_out, int out_size) {
    const float* z  = (const float*)d_in[0];
    const float* y  = (const float*)d_in[1];
    const float* Wq = (const float*)d_in[2];
    const float* bq = (const float*)d_in[3];
    const float* Wk = (const float*)d_in[4];
    const float* bk = (const float*)d_in[5];
    const float* Wv = (const float*)d_in[6];
    const float* bv = (const float*)d_in[7];
    const float* Wo = (const float*)d_in[8];
    const float* bo = (const float*)d_in[9];
    float* out = (float*)d_out;

    __half *pMT, *pTWo, *pWvH, *pTWq, *pTWk, *pzh, *pyh, *pQh, *pKh, *pUT, *pPh;
    float *pc;
    cudaGetSymbolAddress((void**)&pMT, g_MT);
    cudaGetSymbolAddress((void**)&pTWo, g_TWo);
    cudaGetSymbolAddress((void**)&pWvH, g_WvH);
    cudaGetSymbolAddress((void**)&pTWq, g_TWq);
    cudaGetSymbolAddress((void**)&pTWk, g_TWk);
    cudaGetSymbolAddress((void**)&pzh, g_zh);
    cudaGetSymbolAddress((void**)&pyh, g_yh);
    cudaGetSymbolAddress((void**)&pQh, g_Qh);
    cudaGetSymbolAddress((void**)&pKh, g_Kh);
    cudaGetSymbolAddress((void**)&pUT, g_UT);
    cudaGetSymbolAddress((void**)&pPh, g_Ph);
    cudaGetSymbolAddress((void**)&pc, g_cvec);

    cudaFuncSetAttribute(nt_gemm<__half>,
                         cudaFuncAttributeMaxDynamicSharedMemorySize, GSMEM);
    cudaFuncSetAttribute(nt_gemm<float>,
                         cudaFuncAttributeMaxDynamicSharedMemorySize, GSMEM);

    // 0) fused prepass + bias fold
    prepass_k<<<34944, 256>>>(z, y, Wv, Wo, Wq, Wk, bv);
    cvec_final_k<<<4, 256>>>(bo);

    // 2) M^T[h] = TWo[h] @ WvH[h]^T              512 tiles, K=16 chunks
    nt_gemm<__half><<<PGRID, 256, GSMEM>>>(
        pTWo, pWvH, pMT, nullptr, 16, 1024, 1024, 1024,
        0, (long long)D_ * D_, 0, (long long)D_ * D_, 0, (long long)D_ * D_,
        8, 0, 1.f, 30, 0, 0, 8, 8, 512);

    // 3) Q[b,h] = yh[b] @ TWq[h]^T + bq          512 tiles
    nt_gemm<__half><<<PGRID, 256, GSMEM>>>(
        pyh, pTWq, pQh, bq, 16, 1024, 1024, 128,
        (long long)S_ * D_, 0, 0, (long long)KQ_ * D_,
        (long long)H_ * S_ * KQ_, (long long)S_ * KQ_, 8, 128, 1.f, 30, 0, 0,
        1, 16, 512);

    // 4) K[b,h] = zh[b] @ TWk[h]^T + bk
    nt_gemm<__half><<<PGRID, 256, GSMEM>>>(
        pzh, pTWk, pKh, bk, 16, 1024, 1024, 128,
        (long long)S_ * D_, 0, 0, (long long)KQ_ * D_,
        (long long)H_ * S_ * KQ_, (long long)S_ * KQ_, 8, 128, 1.f, 30, 0, 0,
        1, 16, 512);

    // 5) U^T[b,h] = MT[h] @ zh[b]^T              4096 tiles  <-- ncu capture (index 5)
    nt_gemm<__half><<<PGRID, 256, GSMEM>>>(
        pMT, pzh, pUT, nullptr, 16, 1024, 1024, 2048,
        0, (long long)D_ * D_, (long long)S_ * D_, 0,
        (long long)H_ * D_ * S_, (long long)D_ * S_, 8, 0, 1.f, 30, 0, 0,
        16, 8, 4096);

    // 6) scores = (Qh @ Kh^T)/sqrt(128), fp16    8192 tiles, K=2 chunks
    nt_gemm<__half><<<PGRID, 256, GSMEM>>>(
        pQh, pKh, pPh, nullptr, 2, 128, 128, 2048,
        (long long)H_ * S_ * KQ_, (long long)S_ * KQ_,
        (long long)H_ * S_ * KQ_, (long long)S_ * KQ_,
        (long long)H_ * S_ * S_, (long long)S_ * S_,
        8, 0, 0.08838834764831845f, 30, 0, 0, 16, 16, 8192);

    // 7) softmax rows (fp16 in place)
    softmax_k<<<B_ * H_ * S_, 256>>>();

    // 8) out = sum_h P_h @ UT_h^T + cvec         512 tiles, K=256 chunks (32/head)
    nt_gemm<float><<<PGRID, 256, GSMEM>>>(
        pPh, pUT, out, pc, 256, 2048, 2048, 1024,
        0, (long long)H_ * S_ * S_, 0, (long long)H_ * D_ * S_,
        0, (long long)S_ * D_, 4, 0, 1.f,
        5, (long long)S_ * S_, (long long)D_ * S_, 8, 16, 512);
}

// round 11
// speedup vs baseline: 1.1401x; 1.0423x over previous
#include <cuda_runtime.h>
#include <cuda_fp16.h>
#include <cstdint>

#define DI __device__ __forceinline__

static constexpr int B_ = 4, H_ = 8, S_ = 2048, D_ = 1024, KQ_ = 128;
static constexpr int PGRID = 296;   // 148 SMs x 2 CTAs

// ---------------- scratch (device globals; no allocations allowed) ----------------
__device__ __half g_MT[(size_t)H_ * D_ * D_];
__device__ __half g_TWo[(size_t)H_ * D_ * D_];
__device__ __half g_WvH[(size_t)H_ * D_ * D_];
__device__ __half g_TWq[(size_t)H_ * KQ_ * D_];
__device__ __half g_TWk[(size_t)H_ * KQ_ * D_];
__device__ __half g_zh[(size_t)B_ * S_ * D_];
__device__ __half g_yh[(size_t)B_ * S_ * D_];
__device__ __half g_Qh[(size_t)B_ * H_ * S_ * KQ_];
__device__ __half g_Kh[(size_t)B_ * H_ * S_ * KQ_];
__device__ __half g_UT[(size_t)B_ * H_ * D_ * S_];   // U^T[b,h][j][t]
__device__ __half g_Ph[(size_t)B_ * H_ * S_ * S_];   // scores / P fp16
__device__ float g_cvec[D_];
__device__ float g_cpart[32 * D_];

// ---------------- helpers ----------------
DI uint32_t smem_u32(const void* p) {
    uint32_t a;
    asm("{ .reg .u64 t; cvta.to.shared.u64 t, %1; cvt.u32.u64 %0, t; }" : "=r"(a) : "l"(p));
    return a;
}
DI void mma_f16(float c[4], uint32_t a0, uint32_t a1, uint32_t a2, uint32_t a3,
                uint32_t b0, uint32_t b1) {
    asm volatile(
        "mma.sync.aligned.m16n8k16.row.col.f32.f16.f16.f32 "
        "{%0,%1,%2,%3}, {%4,%5,%6,%7}, {%8,%9}, {%0,%1,%2,%3};"
        : "+f"(c[0]), "+f"(c[1]), "+f"(c[2]), "+f"(c[3])
        : "r"(a0), "r"(a1), "r"(a2), "r"(a3), "r"(b0), "r"(b1));
}
DI void ldsm4(uint32_t r[4], uint32_t a) {
    asm volatile("ldmatrix.sync.aligned.m8n8.x4.shared.b16 {%0,%1,%2,%3}, [%4];"
                 : "=r"(r[0]), "=r"(r[1]), "=r"(r[2]), "=r"(r[3]) : "r"(a));
}
DI void cp16(uint32_t d, const void* s) {
    asm volatile("cp.async.cg.shared.global [%0], [%1], 16;" :: "r"(d), "l"(s));
}
DI void cp_commit() { asm volatile("cp.async.commit_group;" ::: "memory"); }

DI void cwrite(__half* p, float a, float b) {
    *reinterpret_cast<__half2*>(p) = __floats2half2_rn(a, b);
}
DI void cwrite(float* p, float a, float b) {
    *reinterpret_cast<float2*>(p) = make_float2(a, b);
}

// ====== fp16 NT GEMM, 128x128 CTA, K-chunk 64 halves, 3-stage cp.async ======
// PERSISTENT with CONTINUOUS cross-tile pipeline: an issue cursor runs 2 chunks
// ahead of the compute cursor across tile boundaries (stage = global_chunk % 3).
// C = alpha * A @ B^T + bias.  A [M,K], B [N,K] fp16 row-major; C fp16/fp32.
// SMEM tile/stage: 128 rows x 64 halves; 16B chunk (r,c∈0..7) at p = r*8 + (c ^ (r&7)).
// head-fused K: chunk c -> h = c>>hshift (offset h*s?h), k-off (c&hmask)*64.
// NOTE: all per-z2 operand extents fit in 32-bit element offsets.
template <typename CT>
__global__ __launch_bounds__(256, 2) void nt_gemm(
    const __half* __restrict__ Ag, const __half* __restrict__ Bg,
    CT* __restrict__ Cg, const float* __restrict__ bias,
    int kchunks, int lda, int ldb, int ldc,
    long long sA1, long long sA2, long long sB1, long long sB2,
    long long sC1, long long sC2, int Z2, int sbias2, float alpha,
    int hshift, int sAh, int sBh,
    int ngx, int ngy, int ntiles)
{
    extern __shared__ __align__(128) uint32_t dyn_smem[];
    const uint32_t sb = smem_u32(dyn_smem);

    const int tid = threadIdx.x, lane = tid & 31, wid = tid >> 5;
    const int wm = (wid & 1) * 64, wn = (wid >> 1) * 32;
    const int g = lane >> 2, q = lane & 3;

    int lr[4], lc[4];
    uint32_t dst[4];
#pragma unroll
    for (int i = 0; i < 4; i++) {
        int qid = tid + i * 256;
        lr[i] = qid >> 3;
        lc[i] = qid & 7;
        dst[i] = (uint32_t)((lr[i] * 8 + (lc[i] ^ (lr[i] & 7))) << 4);
    }

    const int l15 = lane & 15, hs = lane >> 4;
    uint32_t arow[4], axor[4], brow[2], bxor[2];
#pragma unroll
    for (int mt = 0; mt < 4; mt++) {
        int rr = wm + mt * 16 + l15;
        arow[mt] = (uint32_t)(rr * 128);
        axor[mt] = (uint32_t)(rr & 7);
    }
#pragma unroll
    for (int np = 0; np < 2; np++) {
        int nn = wn + np * 16 + l15;
        brow[np] = (uint32_t)(nn * 128);
        bxor[np] = (uint32_t)(nn & 7);
    }

    const int hmask = (hshift < 30) ? ((1 << hshift) - 1) : 0x3FFFFFFF;
    const int nxy = ngx * ngy;

    // ---- issue-side cursor (2 chunks ahead, runs across tile boundaries) ----
    int i_tile = blockIdx.x, i_chunk = 0;
    const __half *iA = Ag, *iB = Bg;
    uint32_t iaoff[4], iboff[4];
    bool has_issue = (i_tile < ntiles);

    auto setupIssue = [&](int t) {
        const int tz = t / nxy, rxy = t - tz * nxy;
        const int tyv = rxy / ngx, txv = rxy - tyv * ngx;
        const int z1 = tz / Z2, z2 = tz - z1 * Z2;
        iA = Ag + z1 * sA1 + z2 * sA2;
        iB = Bg + z1 * sB1 + z2 * sB2;
        const int bm = tyv * 128, bn = txv * 128;
#pragma unroll
        for (int i = 0; i < 4; i++) {
            iaoff[i] = (uint32_t)((bm + lr[i]) * lda + lc[i] * 8);
            iboff[i] = (uint32_t)((bn + lr[i]) * ldb + lc[i] * 8);
        }
    };
    if (has_issue) setupIssue(i_tile);

    uint32_t gi = 0;
    auto issueOne = [&]() {
        const uint32_t st = gi % 3u;
        const uint32_t koA = (uint32_t)(i_chunk >> hshift) * (uint32_t)sAh +
                             (uint32_t)(i_chunk & hmask) * 64u;
        const uint32_t koB = (uint32_t)(i_chunk >> hshift) * (uint32_t)sBh +
                             (uint32_t)(i_chunk & hmask) * 64u;
        const __half* Ac = iA + koA;
        const __half* Bc = iB + koB;
        const uint32_t a0 = sb + st * 32768, b0 = a0 + 16384;
#pragma unroll
        for (int i = 0; i < 4; i++) {
            cp16(a0 + dst[i], Ac + iaoff[i]);
            cp16(b0 + dst[i], Bc + iboff[i]);
        }
        cp_commit();
        gi++;
        if (++i_chunk == kchunks) {
            i_chunk = 0;
            i_tile += gridDim.x;
            if (i_tile < ntiles) setupIssue(i_tile);
            else has_issue = false;
        }
    };
    if (has_issue) issueOne();
    if (has_issue) issueOne();

    // ---- compute-side loop ----
    uint32_t gc = 0;
    for (int ct = blockIdx.x; ct < ntiles; ct += gridDim.x) {
        const int tz = ct / nxy, rxy = ct - tz * nxy;
        const int tyv = rxy / ngx, txv = rxy - tyv * ngx;
        const int z1 = tz / Z2, z2 = tz - z1 * Z2;
        CT* C = Cg + z1 * sC1 + z2 * sC2;
        const int bm = tyv * 128, bn = txv * 128;

        float acc[4][4][4];
#pragma unroll
        for (int i = 0; i < 4; i++)
#pragma unroll
            for (int j = 0; j < 4; j++)
#pragma unroll
                for (int k = 0; k < 4; k++) acc[i][j][k] = 0.f;

        for (int c = 0; c < kchunks; c++) {
            if (gi > gc + 1)
                asm volatile("cp.async.wait_group 1;" ::: "memory");
            else
                asm volatile("cp.async.wait_group 0;" ::: "memory");
            __syncthreads();
            if (has_issue) issueOne();

            const uint32_t st = gc % 3u;
            const uint32_t aB = sb + st * 32768, bB = aB + 16384;
#pragma unroll
            for (int s = 0; s < 4; s++) {
                uint32_t af[4][4], bf[4][2];
                const uint32_t cc = (uint32_t)(2 * s + hs);
#pragma unroll
                for (int mt = 0; mt < 4; mt++)
                    ldsm4(af[mt], aB + arow[mt] + ((cc ^ axor[mt]) << 4));
#pragma unroll
                for (int np = 0; np < 2; np++) {
                    uint32_t t4[4];
                    ldsm4(t4, bB + brow[np] + ((cc ^ bxor[np]) << 4));
                    bf[2 * np][0] = t4[0];
                    bf[2 * np][1] = t4[2];
                    bf[2 * np + 1][0] = t4[1];
                    bf[2 * np + 1][1] = t4[3];
                }
#pragma unroll
                for (int mt = 0; mt < 4; mt++)
#pragma unroll
                    for (int nt = 0; nt < 4; nt++)
                        mma_f16(acc[mt][nt], af[mt][0], af[mt][1], af[mt][2], af[mt][3],
                                bf[nt][0], bf[nt][1]);
            }
            gc++;
        }

        const float* bp = bias ? bias + (long long)z2 * sbias2 : nullptr;
#pragma unroll
        for (int mt = 0; mt < 4; mt++) {
#pragma unroll
            for (int nt = 0; nt < 4; nt++) {
                int r = bm + wm + mt * 16 + g;
                int cc = bn + wn + nt * 8 + q * 2;
                float b0v = bp ? bp[cc] : 0.f;
                float b1v = bp ? bp[cc + 1] : 0.f;
                cwrite(C + (long long)r * ldc + cc,
                       alpha * acc[mt][nt][0] + b0v, alpha * acc[mt][nt][1] + b1v);
                cwrite(C + (long long)(r + 8) * ldc + cc,
                       alpha * acc[mt][nt][2] + b0v, alpha * acc[mt][nt][3] + b1v);
            }
        }
        // no trailing __syncthreads: epilogue touches no smem; stage reuse is
        // protected by the per-chunk barriers of the next tile's mainloop.
    }
}

// ============ fused prepass: converts + transposes + cvec partial (one kernel) ============
__global__ __launch_bounds__(256) void prepass_k(
    const float* __restrict__ z, const float* __restrict__ y,
    const float* __restrict__ Wv, const float* __restrict__ Wo,
    const float* __restrict__ Wq, const float* __restrict__ Wk,
    const float* __restrict__ bv)
{
    __shared__ float t[32][33];
    const int b = blockIdx.x, tid = threadIdx.x;

    if (b < 24576) {
        const float* in;
        __half* out;
        int i;
        if (b < 8192)       { in = z;  out = g_zh;  i = b * 256 + tid; }
        else if (b < 16384) { in = y;  out = g_yh;  i = (b - 8192) * 256 + tid; }
        else                { in = Wv; out = g_WvH; i = (b - 16384) * 256 + tid; }
        float4 v = reinterpret_cast<const float4*>(in)[i];
        __half2 h0 = __floats2half2_rn(v.x, v.y);
        __half2 h1 = __floats2half2_rn(v.z, v.w);
        uint2 u;
        u.x = *reinterpret_cast<uint32_t*>(&h0);
        u.y = *reinterpret_cast<uint32_t*>(&h1);
        reinterpret_cast<uint2*>(out)[i] = u;
        return;
    }
    if (b < 34816) {
        const float* in;
        __half* out;
        int R, C, idx;
        if (b < 32768)      { in = Wo; out = g_TWo; R = 1024; C = 1024; idx = b - 24576; }
        else if (b < 33792) { in = Wq; out = g_TWq; R = 1024; C = 128;  idx = b - 32768; }
        else                { in = Wk; out = g_TWk; R = 1024; C = 128;  idx = b - 33792; }
        const int ngx = C / 32;
        const int h = idx / (ngx * 32);
        const int rxy = idx - h * (ngx * 32);
        const int byi = rxy / ngx, bxi = rxy - byi * ngx;
        const float* ip = in + (size_t)h * R * C;
        __half* op = out + (size_t)h * R * C;
        int bx = bxi * 32, by = byi * 32;
        int tx = tid & 31, ty = tid >> 5;
#pragma unroll
        for (int j = 0; j < 32; j += 8)
            t[ty + j][tx] = ip[(size_t)(by + ty + j) * C + bx + tx];
        __syncthreads();
#pragma unroll
        for (int j = 0; j < 32; j += 8)
            op[(size_t)(bx + ty + j) * R + by + tx] = __float2half(t[tx][ty + j]);
        return;
    }
    {
        const int idx = b - 34816;          // 0..127
        const int j = (idx & 3) * 256 + tid;
        const int r0 = (idx >> 2) * 256;
        float acc = 0.f;
        for (int r = r0; r < r0 + 256; r++) acc += bv[r] * Wo[(size_t)r * D_ + j];
        g_cpart[(idx >> 2) * D_ + j] = acc;
    }
}

__global__ void cvec_final_k(const float* __restrict__ bo) {
    int j = blockIdx.x * 256 + threadIdx.x;
    float acc = bo[j];
    for (int r = 0; r < 32; r++) acc += g_cpart[r * D_ + j];
    g_cvec[j] = acc;
}

// ------- row softmax on fp16 scores, in place -------
__global__ __launch_bounds__(256) void softmax_k() {
    __half* row = g_Ph + (size_t)blockIdx.x * S_;
    int tid = threadIdx.x;
    uint4 u = *reinterpret_cast<const uint4*>(row + tid * 8);
    float v[8];
    {
        __half2* hp = reinterpret_cast<__half2*>(&u);
#pragma unroll
        for (int i = 0; i < 4; i++) {
            float2 f = __half22float2(hp[i]);
            v[2 * i] = f.x;
            v[2 * i + 1] = f.y;
        }
    }
    float mx = -1e30f;
#pragma unroll
    for (int i = 0; i < 8; i++) mx = fmaxf(mx, v[i]);
#pragma unroll
    for (int o = 16; o > 0; o >>= 1) mx = fmaxf(mx, __shfl_xor_sync(0xffffffffu, mx, o));
    __shared__ float red[8];
    if ((tid & 31) == 0) red[tid >> 5] = mx;
    __syncthreads();
    mx = red[0];
#pragma unroll
    for (int wi = 1; wi < 8; wi++) mx = fmaxf(mx, red[wi]);

    float s = 0.f;
#pragma unroll
    for (int i = 0; i < 8; i++) {
        v[i] = exp2f((v[i] - mx) * 1.4426950408889634f);
        s += v[i];
    }
#pragma unroll
    for (int o = 16; o > 0; o >>= 1) s += __shfl_xor_sync(0xffffffffu, s, o);
    __syncthreads();
    if ((tid & 31) == 0) red[tid >> 5] = s;
    __syncthreads();
    s = 0.f;
#pragma unroll
    for (int wi = 0; wi < 8; wi++) s += red[wi];
    float inv = 1.f / s;

    __half2 p0 = __floats2half2_rn(v[0] * inv, v[1] * inv);
    __half2 p1 = __floats2half2_rn(v[2] * inv, v[3] * inv);
    __half2 p2 = __floats2half2_rn(v[4] * inv, v[5] * inv);
    __half2 p3 = __floats2half2_rn(v[6] * inv, v[7] * inv);
    uint4 o;
    o.x = *reinterpret_cast<uint32_t*>(&p0);
    o.y = *reinterpret_cast<uint32_t*>(&p1);
    o.z = *reinterpret_cast<uint32_t*>(&p2);
    o.w = *reinterpret_cast<uint32_t*>(&p3);
    *reinterpret_cast<uint4*>(row + tid * 8) = o;
}

// ---------------- launch ----------------
static constexpr int GSMEM = 98304;   // 3 stages x 32KB

extern "C" void kernel_launch(void* const* d_in, const int* in_sizes, int n_in,
                              void* d_out, int out_size) {
    const float* z  = (const float*)d_in[0];
    const float* y  = (const float*)d_in[1];
    const float* Wq = (const float*)d_in[2];
    const float* bq = (const float*)d_in[3];
    const float* Wk = (const float*)d_in[4];
    const float* bk = (const float*)d_in[5];
    const float* Wv = (const float*)d_in[6];
    const float* bv = (const float*)d_in[7];
    const float* Wo = (const float*)d_in[8];
    const float* bo = (const float*)d_in[9];
    float* out = (float*)d_out;

    __half *pMT, *pTWo, *pWvH, *pTWq, *pTWk, *pzh, *pyh, *pQh, *pKh, *pUT, *pPh;
    float *pc;
    cudaGetSymbolAddress((void**)&pMT, g_MT);
    cudaGetSymbolAddress((void**)&pTWo, g_TWo);
    cudaGetSymbolAddress((void**)&pWvH, g_WvH);
    cudaGetSymbolAddress((void**)&pTWq, g_TWq);
    cudaGetSymbolAddress((void**)&pTWk, g_TWk);
    cudaGetSymbolAddress((void**)&pzh, g_zh);
    cudaGetSymbolAddress((void**)&pyh, g_yh);
    cudaGetSymbolAddress((void**)&pQh, g_Qh);
    cudaGetSymbolAddress((void**)&pKh, g_Kh);
    cudaGetSymbolAddress((void**)&pUT, g_UT);
    cudaGetSymbolAddress((void**)&pPh, g_Ph);
    cudaGetSymbolAddress((void**)&pc, g_cvec);

    cudaFuncSetAttribute(nt_gemm<__half>,
                         cudaFuncAttributeMaxDynamicSharedMemorySize, GSMEM);
    cudaFuncSetAttribute(nt_gemm<float>,
                         cudaFuncAttributeMaxDynamicSharedMemorySize, GSMEM);

    // 0) fused prepass + bias fold
    prepass_k<<<34944, 256>>>(z, y, Wv, Wo, Wq, Wk, bv);
    cvec_final_k<<<4, 256>>>(bo);

    // 2) M^T[h] = TWo[h] @ WvH[h]^T              512 tiles, K=16 chunks
    nt_gemm<__half><<<PGRID, 256, GSMEM>>>(
        pTWo, pWvH, pMT, nullptr, 16, 1024, 1024, 1024,
        0, (long long)D_ * D_, 0, (long long)D_ * D_, 0, (long long)D_ * D_,
        8, 0, 1.f, 30, 0, 0, 8, 8, 512);

    // 3) Q[b,h] = yh[b] @ TWq[h]^T + bq          512 tiles
    nt_gemm<__half><<<PGRID, 256, GSMEM>>>(
        pyh, pTWq, pQh, bq, 16, 1024, 1024, 128,
        (long long)S_ * D_, 0, 0, (long long)KQ_ * D_,
        (long long)H_ * S_ * KQ_, (long long)S_ * KQ_, 8, 128, 1.f, 30, 0, 0,
        1, 16, 512);

    // 4) K[b,h] = zh[b] @ TWk[h]^T + bk
    nt_gemm<__half><<<PGRID, 256, GSMEM>>>(
        pzh, pTWk, pKh, bk, 16, 1024, 1024, 128,
        (long long)S_ * D_, 0, 0, (long long)KQ_ * D_,
        (long long)H_ * S_ * KQ_, (long long)S_ * KQ_, 8, 128, 1.f, 30, 0, 0,
        1, 16, 512);

    // 5) U^T[b,h] = MT[h] @ zh[b]^T              4096 tiles  <-- ncu capture
    nt_gemm<__half><<<PGRID, 256, GSMEM>>>(
        pMT, pzh, pUT, nullptr, 16, 1024, 1024, 2048,
        0, (long long)D_ * D_, (long long)S_ * D_, 0,
        (long long)H_ * D_ * S_, (long long)D_ * S_, 8, 0, 1.f, 30, 0, 0,
        16, 8, 4096);

    // 6) scores = (Qh @ Kh^T)/sqrt(128), fp16    8192 tiles, K=2 chunks
    nt_gemm<__half><<<PGRID, 256, GSMEM>>>(
        pQh, pKh, pPh, nullptr, 2, 128, 128, 2048,
        (long long)H_ * S_ * KQ_, (long long)S_ * KQ_,
        (long long)H_ * S_ * KQ_, (long long)S_ * KQ_,
        (long long)H_ * S_ * S_, (long long)S_ * S_,
        8, 0, 0.08838834764831845f, 30, 0, 0, 16, 16, 8192);

    // 7) softmax rows (fp16 in place)
    softmax_k<<<B_ * H_ * S_, 256>>>();

    // 8) out = sum_h P_h @ UT_h^T + cvec         512 tiles, K=256 chunks (32/head)
    nt_gemm<float><<<PGRID, 256, GSMEM>>>(
        pPh, pUT, out, pc, 256, 2048, 2048, 1024,
        0, (long long)H_ * S_ * S_, 0, (long long)H_ * D_ * S_,
        0, (long long)S_ * D_, 4, 0, 1.f,
        5, S_ * S_, D_ * S_, 8, 16, 512);
}